// round 6
// baseline (speedup 1.0000x reference)
#include <cuda_runtime.h>
#include <cuda_bf16.h>

// Problem constants
#define B    8
#define HIN  256
#define WIN  256
#define CV4  16      // C/4 float4 chunks per pixel (C=64)
#define HP   64
#define WP   64

// 8 MB pooled averages — static device scratch
__device__ float4 g_pooled[B * HP * WP * CV4];

__device__ __forceinline__ void acc4(float4& a, const float4 v) {
    a.x += v.x; a.y += v.y; a.z += v.z; a.w += v.w;
}
__device__ __forceinline__ float4 blend2(float4 p, float wp, float4 q, float wq) {
    float4 r;
    r.x = p.x * wp + q.x * wq;
    r.y = p.y * wp + q.y * wq;
    r.z = p.z * wp + q.z * wq;
    r.w = p.w * wp + q.w * wq;
    return r;
}

// ---------------------------------------------------------------------------
// K1: fused SAME avg-pool 6x6 stride 4 (unchanged from R5 — proven).
// ---------------------------------------------------------------------------
__global__ __launch_bounds__(288) void pool_kernel(const float4* __restrict__ in4) {
    __shared__ float4 cs[18 * CV4];   // [xl][c4]

    int bid = blockIdx.x;             // b*1024 + oy*16 + q
    int q  = bid & 15;
    int oy = (bid >> 4) & 63;
    int b  = bid >> 10;

    int t  = threadIdx.x;             // 0..287
    int c4 = t & 15;
    int xl = t >> 4;                  // 0..17
    int x  = 16 * q - 1 + xl;
    int r0 = 4 * oy - 1;

    float4 s = make_float4(0.f, 0.f, 0.f, 0.f);
    if ((unsigned)x < 256u) {
        const float4* p = in4 + (((size_t)b * HIN) * WIN + x) * CV4 + c4;
        if (oy != 0 && oy != 63) {
            const float4* qq = p + (size_t)r0 * WIN * CV4;
            #pragma unroll
            for (int j = 0; j < 6; ++j)
                acc4(s, __ldg(qq + (size_t)j * WIN * CV4));
        } else {
            #pragma unroll
            for (int j = 0; j < 6; ++j) {
                int r = r0 + j;
                if ((unsigned)r < 256u)
                    acc4(s, __ldg(p + (size_t)r * WIN * CV4));
            }
        }
    }
    cs[t] = s;
    __syncthreads();

    if (t < 64) {
        int oxl = t >> 4;             // 0..3
        int ox  = 4 * q + oxl;

        float4 acc = make_float4(0.f, 0.f, 0.f, 0.f);
        if (ox != 0) acc4(acc, cs[(4 * oxl + 0) * CV4 + c4]);
        acc4(acc, cs[(4 * oxl + 1) * CV4 + c4]);
        acc4(acc, cs[(4 * oxl + 2) * CV4 + c4]);
        acc4(acc, cs[(4 * oxl + 3) * CV4 + c4]);
        acc4(acc, cs[(4 * oxl + 4) * CV4 + c4]);
        if (ox != 63) acc4(acc, cs[(4 * oxl + 5) * CV4 + c4]);

        int nr = 6 - (oy == 0) - (oy == 63);
        int nc = 6 - (ox == 0) - (ox == 63);
        float inv = 1.0f / (float)(nr * nc);
        g_pooled[(((size_t)b * HP + oy) * WP + ox) * CV4 + c4] =
            make_float4(acc.x * inv, acc.y * inv, acc.z * inv, acc.w * inv);
    }
}

// ---------------------------------------------------------------------------
// K2: unaverage pool with smem-staged pooled tile.
// CTA = (b, y, x-half). Needed pooled data: rows {r0, r0+1} x cols
// [32h-1 .. 32h+32] (34, halo zeroed) x 16 c4 = 17.4 KB smem.
// Load coalesced once (4.25 LDG/thread), then 8 LDS + FFMA-imm + 8 STG.
// ---------------------------------------------------------------------------
__device__ __forceinline__ float d2s(float d) {
    if (d < 5.5f)   return (d - 2.0f) * (1.0f / 3.5f);
    if (d > 249.5f) return (d - 249.5f) * (1.0f / 3.5f) + 62.0f;
    return (d - 1.5f) * 0.25f;
}

#define UP_TILE_TASKS (34 * 2 * CV4)   // 1088: [col_l][row][c4]

__global__ __launch_bounds__(256) void up_kernel(float4* __restrict__ out4) {
    __shared__ float4 sm[UP_TILE_TASKS];

    int bid = blockIdx.x;              // b*512 + y*2 + h
    int h = bid & 1;
    int y = (bid >> 1) & 255;
    int b = bid >> 9;
    int t = threadIdx.x;

    // Row mapping (uniform per CTA)
    float sr  = d2s((float)y);
    float r0f = floorf(sr);
    int   r0  = (int)r0f;
    float fr  = sr - r0f;
    bool rv0 = (r0 >= 0);
    bool rv1 = (r0 < HP - 1);
    float wr0 = 1.0f - fr;

    const float4* pbase = g_pooled + ((size_t)b * HP * WP) * CV4;
    const float4* rowA  = pbase + (size_t)(rv0 ? r0     : 0) * WP * CV4;
    const float4* rowB  = pbase + (size_t)(rv1 ? r0 + 1 : 0) * WP * CV4;
    const float4 z = make_float4(0.f, 0.f, 0.f, 0.f);

    int colbase = 32 * h - 1;          // global col of col_l = 0

    // Stage tile: w -> c4 = w&15, row = (w>>4)&1, col_l = w>>5
    #pragma unroll 1
    for (int w = t; w < UP_TILE_TASKS; w += 256) {
        int c4    = w & 15;
        int row   = (w >> 4) & 1;
        int col_l = w >> 5;
        int col   = colbase + col_l;
        bool cv   = (unsigned)col < (unsigned)WP;
        float4 v = z;
        if (cv) {
            if (row == 0) { if (rv0) v = __ldg(rowA + (size_t)col * CV4 + c4); }
            else          { if (rv1) v = __ldg(rowB + (size_t)col * CV4 + c4); }
        }
        sm[w] = v;
    }
    __syncthreads();

    // Compute: thread -> (c4, kk_l); k0 = 32h + 2*kk_l
    int c4   = t & 15;
    int kk_l = t >> 4;                 // 0..15
    int k0   = 32 * h + 2 * kk_l;
    int kk   = 16 * h + kk_l;          // global k-pair index 0..31

    // Taps T[i] = row-blend of col (k0-1+i) -> smem col_l = 2*kk_l + i
    float4 T[4];
    #pragma unroll
    for (int i = 0; i < 4; ++i) {
        int cl = 2 * kk_l + i;
        float4 a  = sm[(cl * 2 + 0) * CV4 + c4];
        float4 bb = sm[(cl * 2 + 1) * CV4 + c4];
        T[i] = blend2(a, wr0, bb, fr);
    }

    float4* op = out4 + (((size_t)b * HIN + y) * WIN + k0 * 4) * CV4 + c4;

    if (kk >= 1 && kk <= 30) {
        op[0 * CV4] = blend2(T[0], 0.375f, T[1], 0.625f);
        op[1 * CV4] = blend2(T[0], 0.125f, T[1], 0.875f);
        op[2 * CV4] = blend2(T[1], 0.875f, T[2], 0.125f);
        op[3 * CV4] = blend2(T[1], 0.625f, T[2], 0.375f);
        op[4 * CV4] = blend2(T[1], 0.375f, T[2], 0.625f);
        op[5 * CV4] = blend2(T[1], 0.125f, T[2], 0.875f);
        op[6 * CV4] = blend2(T[2], 0.875f, T[3], 0.125f);
        op[7 * CV4] = blend2(T[2], 0.625f, T[3], 0.375f);
    } else {
        int x0 = k0 * 4;
        #pragma unroll
        for (int m = 0; m < 8; ++m) {
            float sc  = d2s((float)(x0 + m));
            float c0f = floorf(sc);
            float fc  = sc - c0f;
            int idx = (int)c0f - (k0 - 1);   // 0..2
            float4 lo = (idx == 0) ? T[0] : ((idx == 1) ? T[1] : T[2]);
            float4 hi = (idx == 0) ? T[1] : ((idx == 1) ? T[2] : T[3]);
            op[m * CV4] = blend2(lo, 1.0f - fc, hi, fc);
        }
    }
}

extern "C" void kernel_launch(void* const* d_in, const int* in_sizes, int n_in,
                              void* d_out, int out_size) {
    const float4* in4 = (const float4*)d_in[0];
    float4* out4 = (float4*)d_out;

    pool_kernel<<<B * HP * 16, 288>>>(in4);   // 8192 CTAs
    up_kernel<<<B * HIN * 2, 256>>>(out4);    // 4096 CTAs
}

// round 7
// speedup vs baseline: 1.1855x; 1.1855x over previous
#include <cuda_runtime.h>
#include <cuda_bf16.h>

// Problem constants
#define B    8
#define HIN  256
#define WIN  256
#define CV4  16      // C/4 float4 chunks per pixel (C=64)
#define HP   64
#define WP   64

// 8 MB pooled averages — static device scratch
__device__ float4 g_pooled[B * HP * WP * CV4];

__device__ __forceinline__ void acc4(float4& a, const float4 v) {
    a.x += v.x; a.y += v.y; a.z += v.z; a.w += v.w;
}
__device__ __forceinline__ float4 blend2(float4 p, float wp, float4 q, float wq) {
    float4 r;
    r.x = p.x * wp + q.x * wq;
    r.y = p.y * wp + q.y * wq;
    r.z = p.z * wp + q.z * wq;
    r.w = p.w * wp + q.w * wq;
    return r;
}

// ---------------------------------------------------------------------------
// K1: fused SAME avg-pool 6x6 stride 4 (R5 structure; row loop split 3+3 to
// reduce front-batched MLP and cross-CTA L1tex-queue spread).
// ---------------------------------------------------------------------------
__global__ __launch_bounds__(288, 7) void pool_kernel(const float4* __restrict__ in4) {
    __shared__ float4 cs[18 * CV4];   // [xl][c4]

    int bid = blockIdx.x;             // b*1024 + oy*16 + q
    int q  = bid & 15;
    int oy = (bid >> 4) & 63;
    int b  = bid >> 10;

    int t  = threadIdx.x;             // 0..287
    int c4 = t & 15;
    int xl = t >> 4;                  // 0..17
    int x  = 16 * q - 1 + xl;
    int r0 = 4 * oy - 1;

    float4 s = make_float4(0.f, 0.f, 0.f, 0.f);
    if ((unsigned)x < 256u) {
        const float4* p = in4 + (((size_t)b * HIN) * WIN + x) * CV4 + c4;
        if (oy != 0 && oy != 63) {
            const float4* qq = p + (size_t)r0 * WIN * CV4;
            // batch 1 (3 loads), accumulate, batch 2 (3 loads)
            float4 v0 = __ldg(qq + 0 * WIN * CV4);
            float4 v1 = __ldg(qq + 1 * WIN * CV4);
            float4 v2 = __ldg(qq + 2 * WIN * CV4);
            acc4(s, v0); acc4(s, v1); acc4(s, v2);
            float4 v3 = __ldg(qq + 3 * WIN * CV4);
            float4 v4 = __ldg(qq + 4 * WIN * CV4);
            float4 v5 = __ldg(qq + 5 * WIN * CV4);
            acc4(s, v3); acc4(s, v4); acc4(s, v5);
        } else {
            #pragma unroll
            for (int j = 0; j < 6; ++j) {
                int r = r0 + j;
                if ((unsigned)r < 256u)
                    acc4(s, __ldg(p + (size_t)r * WIN * CV4));
            }
        }
    }
    cs[t] = s;
    __syncthreads();

    if (t < 64) {
        int oxl = t >> 4;             // 0..3
        int ox  = 4 * q + oxl;

        float4 acc = make_float4(0.f, 0.f, 0.f, 0.f);
        if (ox != 0) acc4(acc, cs[(4 * oxl + 0) * CV4 + c4]);
        acc4(acc, cs[(4 * oxl + 1) * CV4 + c4]);
        acc4(acc, cs[(4 * oxl + 2) * CV4 + c4]);
        acc4(acc, cs[(4 * oxl + 3) * CV4 + c4]);
        acc4(acc, cs[(4 * oxl + 4) * CV4 + c4]);
        if (ox != 63) acc4(acc, cs[(4 * oxl + 5) * CV4 + c4]);

        int nr = 6 - (oy == 0) - (oy == 63);
        int nc = 6 - (ox == 0) - (ox == 63);
        float inv = 1.0f / (float)(nr * nc);
        g_pooled[(((size_t)b * HP + oy) * WP + ox) * CV4 + c4] =
            make_float4(acc.x * inv, acc.y * inv, acc.z * inv, acc.w * inv);
    }
}

// ---------------------------------------------------------------------------
// K2: unaverage pool, direct (R5-proven) + occupancy bump (6 CTAs/SM -> 75%).
// One thread = 8 consecutive x outputs (two k-groups) x one float4 chunk.
// ---------------------------------------------------------------------------
__device__ __forceinline__ float d2s(float d) {
    if (d < 5.5f)   return (d - 2.0f) * (1.0f / 3.5f);
    if (d > 249.5f) return (d - 249.5f) * (1.0f / 3.5f) + 62.0f;
    return (d - 1.5f) * 0.25f;
}

__global__ __launch_bounds__(256, 6) void up_kernel(float4* __restrict__ out4) {
    int tid = blockIdx.x * 256 + threadIdx.x;   // B*256*32*16 = 1,048,576
    int c4 = tid & 15;
    int kk = (tid >> 4) & 31;
    int y  = (tid >> 9) & 255;
    int b  = tid >> 17;

    int k0 = kk * 2;

    float sr  = d2s((float)y);
    float r0f = floorf(sr);
    int   r0  = (int)r0f;
    float fr  = sr - r0f;
    bool rv0 = (r0 >= 0);
    bool rv1 = (r0 < HP - 1);
    float wr0 = 1.0f - fr;

    const float4* pbase = g_pooled + ((size_t)b * HP * WP) * CV4 + c4;
    const float4* rowA  = pbase + (size_t)(rv0 ? r0     : 0) * WP * CV4;
    const float4* rowB  = pbase + (size_t)(rv1 ? r0 + 1 : 0) * WP * CV4;

    const float4 z = make_float4(0.f, 0.f, 0.f, 0.f);

    float4 T[4];
    #pragma unroll
    for (int i = 0; i < 4; ++i) {
        int col = k0 - 1 + i;
        bool cv = (unsigned)col < (unsigned)WP;
        float4 a  = (rv0 && cv) ? __ldg(rowA + (size_t)col * CV4) : z;
        float4 bb = (rv1 && cv) ? __ldg(rowB + (size_t)col * CV4) : z;
        T[i] = blend2(a, wr0, bb, fr);
    }

    float4* op = out4 + (((size_t)b * HIN + y) * WIN + k0 * 4) * CV4 + c4;

    if (kk >= 1 && kk <= 30) {
        op[0 * CV4] = blend2(T[0], 0.375f, T[1], 0.625f);
        op[1 * CV4] = blend2(T[0], 0.125f, T[1], 0.875f);
        op[2 * CV4] = blend2(T[1], 0.875f, T[2], 0.125f);
        op[3 * CV4] = blend2(T[1], 0.625f, T[2], 0.375f);
        op[4 * CV4] = blend2(T[1], 0.375f, T[2], 0.625f);
        op[5 * CV4] = blend2(T[1], 0.125f, T[2], 0.875f);
        op[6 * CV4] = blend2(T[2], 0.875f, T[3], 0.125f);
        op[7 * CV4] = blend2(T[2], 0.625f, T[3], 0.375f);
    } else {
        int x0 = k0 * 4;
        #pragma unroll
        for (int m = 0; m < 8; ++m) {
            float sc  = d2s((float)(x0 + m));
            float c0f = floorf(sc);
            float fc  = sc - c0f;
            int idx = (int)c0f - (k0 - 1);   // 0..2
            float4 lo = (idx == 0) ? T[0] : ((idx == 1) ? T[1] : T[2]);
            float4 hi = (idx == 0) ? T[1] : ((idx == 1) ? T[2] : T[3]);
            op[m * CV4] = blend2(lo, 1.0f - fc, hi, fc);
        }
    }
}

extern "C" void kernel_launch(void* const* d_in, const int* in_sizes, int n_in,
                              void* d_out, int out_size) {
    const float4* in4 = (const float4*)d_in[0];
    float4* out4 = (float4*)d_out;

    pool_kernel<<<B * HP * 16, 288>>>(in4);               // 8192 CTAs
    up_kernel<<<(B * HIN * 32 * CV4) / 256, 256>>>(out4); // 4096 CTAs
}

// round 8
// speedup vs baseline: 1.1905x; 1.0042x over previous
#include <cuda_runtime.h>
#include <cuda_bf16.h>

// Problem constants
#define B    8
#define HIN  256
#define WIN  256
#define CV4  16      // C/4 float4 chunks per pixel (C=64)
#define HP   64
#define WP   64

// 8 MB pooled averages — static device scratch
__device__ float4 g_pooled[B * HP * WP * CV4];

__device__ __forceinline__ void acc4(float4& a, const float4 v) {
    a.x += v.x; a.y += v.y; a.z += v.z; a.w += v.w;
}
__device__ __forceinline__ float4 blend2(float4 p, float wp, float4 q, float wq) {
    float4 r;
    r.x = p.x * wp + q.x * wq;
    r.y = p.y * wp + q.y * wq;
    r.z = p.z * wp + q.z * wq;
    r.w = p.w * wp + q.w * wq;
    return r;
}

// ---------------------------------------------------------------------------
// K1: fused SAME avg-pool 6x6 stride 4, oy-PAIR per CTA.
// CTA = (b, oy-pair p, ox-quad q). The two y-windows (oy=2p, 2p+1) cover 10
// distinct input rows (rows 4..5 shared) -> load each row once:
//   s0 = rows 0..5, s1 = rows 4..9 (of rbase = 8p-1).
// Phase 2: 128 threads row-pool 2x64 outputs from smem.
// ---------------------------------------------------------------------------
__global__ __launch_bounds__(288, 5) void pool_kernel(const float4* __restrict__ in4) {
    __shared__ float4 cs[2 * 288];    // [half][xl*16+c4]

    int bid = blockIdx.x;             // b*512 + p*16 + q
    int q = bid & 15;
    int p = (bid >> 4) & 31;
    int b = bid >> 9;

    int t  = threadIdx.x;             // 0..287
    int c4 = t & 15;
    int xl = t >> 4;                  // 0..17
    int x  = 16 * q - 1 + xl;
    int rbase = 8 * p - 1;

    float4 s0 = make_float4(0.f, 0.f, 0.f, 0.f);
    float4 s1 = make_float4(0.f, 0.f, 0.f, 0.f);

    if ((unsigned)x < 256u) {
        const float4* pr = in4 + (((size_t)b * HIN + rbase) * WIN + x) * CV4 + c4;
        const size_t RS = (size_t)WIN * CV4;
        if (p != 0 && p != 31) {
            // all 10 rows valid
            float4 v0 = __ldg(pr + 0 * RS);
            float4 v1 = __ldg(pr + 1 * RS);
            float4 v2 = __ldg(pr + 2 * RS);
            float4 v3 = __ldg(pr + 3 * RS);
            acc4(s0, v0); acc4(s0, v1); acc4(s0, v2); acc4(s0, v3);
            float4 v4 = __ldg(pr + 4 * RS);
            float4 v5 = __ldg(pr + 5 * RS);
            acc4(s0, v4); acc4(s0, v5);
            acc4(s1, v4); acc4(s1, v5);
            float4 v6 = __ldg(pr + 6 * RS);
            float4 v7 = __ldg(pr + 7 * RS);
            float4 v8 = __ldg(pr + 8 * RS);
            float4 v9 = __ldg(pr + 9 * RS);
            acc4(s1, v6); acc4(s1, v7); acc4(s1, v8); acc4(s1, v9);
        } else {
            #pragma unroll
            for (int j = 0; j < 10; ++j) {
                int r = rbase + j;
                if ((unsigned)r < 256u) {
                    float4 v = __ldg(pr + (size_t)j * RS);
                    if (j <= 5) acc4(s0, v);
                    if (j >= 4) acc4(s1, v);
                }
            }
        }
    }
    cs[t]       = s0;
    cs[288 + t] = s1;
    __syncthreads();

    // Phase 2: t < 128 -> (half, oxl, c4)
    if (t < 128) {
        int cc4  = t & 15;
        int oxl  = (t >> 4) & 3;
        int half = t >> 6;            // 0 or 1
        int ox   = 4 * q + oxl;
        int oy   = 2 * p + half;

        const float4* base = cs + half * 288;
        float4 acc = make_float4(0.f, 0.f, 0.f, 0.f);
        if (ox != 0) acc4(acc, base[(4 * oxl + 0) * CV4 + cc4]);
        acc4(acc, base[(4 * oxl + 1) * CV4 + cc4]);
        acc4(acc, base[(4 * oxl + 2) * CV4 + cc4]);
        acc4(acc, base[(4 * oxl + 3) * CV4 + cc4]);
        acc4(acc, base[(4 * oxl + 4) * CV4 + cc4]);
        if (ox != 63) acc4(acc, base[(4 * oxl + 5) * CV4 + cc4]);

        int nr = 6 - (oy == 0) - (oy == 63);
        int nc = 6 - (ox == 0) - (ox == 63);
        float inv = 1.0f / (float)(nr * nc);
        g_pooled[(((size_t)b * HP + oy) * WP + ox) * CV4 + cc4] =
            make_float4(acc.x * inv, acc.y * inv, acc.z * inv, acc.w * inv);
    }
}

// ---------------------------------------------------------------------------
// K2: unaverage pool, direct (R7-proven: 22.9us).
// One thread = 8 consecutive x outputs (two k-groups) x one float4 chunk.
// ---------------------------------------------------------------------------
__device__ __forceinline__ float d2s(float d) {
    if (d < 5.5f)   return (d - 2.0f) * (1.0f / 3.5f);
    if (d > 249.5f) return (d - 249.5f) * (1.0f / 3.5f) + 62.0f;
    return (d - 1.5f) * 0.25f;
}

__global__ __launch_bounds__(256, 6) void up_kernel(float4* __restrict__ out4) {
    int tid = blockIdx.x * 256 + threadIdx.x;   // B*256*32*16 = 1,048,576
    int c4 = tid & 15;
    int kk = (tid >> 4) & 31;
    int y  = (tid >> 9) & 255;
    int b  = tid >> 17;

    int k0 = kk * 2;

    float sr  = d2s((float)y);
    float r0f = floorf(sr);
    int   r0  = (int)r0f;
    float fr  = sr - r0f;
    bool rv0 = (r0 >= 0);
    bool rv1 = (r0 < HP - 1);
    float wr0 = 1.0f - fr;

    const float4* pbase = g_pooled + ((size_t)b * HP * WP) * CV4 + c4;
    const float4* rowA  = pbase + (size_t)(rv0 ? r0     : 0) * WP * CV4;
    const float4* rowB  = pbase + (size_t)(rv1 ? r0 + 1 : 0) * WP * CV4;

    const float4 z = make_float4(0.f, 0.f, 0.f, 0.f);

    float4 T[4];
    #pragma unroll
    for (int i = 0; i < 4; ++i) {
        int col = k0 - 1 + i;
        bool cv = (unsigned)col < (unsigned)WP;
        float4 a  = (rv0 && cv) ? __ldg(rowA + (size_t)col * CV4) : z;
        float4 bb = (rv1 && cv) ? __ldg(rowB + (size_t)col * CV4) : z;
        T[i] = blend2(a, wr0, bb, fr);
    }

    float4* op = out4 + (((size_t)b * HIN + y) * WIN + k0 * 4) * CV4 + c4;

    if (kk >= 1 && kk <= 30) {
        op[0 * CV4] = blend2(T[0], 0.375f, T[1], 0.625f);
        op[1 * CV4] = blend2(T[0], 0.125f, T[1], 0.875f);
        op[2 * CV4] = blend2(T[1], 0.875f, T[2], 0.125f);
        op[3 * CV4] = blend2(T[1], 0.625f, T[2], 0.375f);
        op[4 * CV4] = blend2(T[1], 0.375f, T[2], 0.625f);
        op[5 * CV4] = blend2(T[1], 0.125f, T[2], 0.875f);
        op[6 * CV4] = blend2(T[2], 0.875f, T[3], 0.125f);
        op[7 * CV4] = blend2(T[2], 0.625f, T[3], 0.375f);
    } else {
        int x0 = k0 * 4;
        #pragma unroll
        for (int m = 0; m < 8; ++m) {
            float sc  = d2s((float)(x0 + m));
            float c0f = floorf(sc);
            float fc  = sc - c0f;
            int idx = (int)c0f - (k0 - 1);   // 0..2
            float4 lo = (idx == 0) ? T[0] : ((idx == 1) ? T[1] : T[2]);
            float4 hi = (idx == 0) ? T[1] : ((idx == 1) ? T[2] : T[3]);
            op[m * CV4] = blend2(lo, 1.0f - fc, hi, fc);
        }
    }
}

extern "C" void kernel_launch(void* const* d_in, const int* in_sizes, int n_in,
                              void* d_out, int out_size) {
    const float4* in4 = (const float4*)d_in[0];
    float4* out4 = (float4*)d_out;

    pool_kernel<<<B * 32 * 16, 288>>>(in4);               // 4096 CTAs
    up_kernel<<<(B * HIN * 32 * CV4) / 256, 256>>>(out4); // 4096 CTAs
}

// round 9
// speedup vs baseline: 1.2012x; 1.0090x over previous
#include <cuda_runtime.h>
#include <cuda_fp16.h>
#include <cuda_bf16.h>

// Problem constants
#define B    8
#define HIN  256
#define WIN  256
#define CV4  16      // C/4 channel chunks per pixel (C=64)
#define HP   64
#define WP   64

// 4 MB pooled averages in fp16 (4 halves per chunk) — static device scratch
__device__ uint2 g_pooled[B * HP * WP * CV4];

__device__ __forceinline__ void acc4(float4& a, const float4 v) {
    a.x += v.x; a.y += v.y; a.z += v.z; a.w += v.w;
}
__device__ __forceinline__ float4 blend2(float4 p, float wp, float4 q, float wq) {
    float4 r;
    r.x = p.x * wp + q.x * wq;
    r.y = p.y * wp + q.y * wq;
    r.z = p.z * wp + q.z * wq;
    r.w = p.w * wp + q.w * wq;
    return r;
}
__device__ __forceinline__ uint2 pack_h4(float4 v) {
    __half2 lo = __floats2half2_rn(v.x, v.y);
    __half2 hi = __floats2half2_rn(v.z, v.w);
    uint2 u;
    u.x = *reinterpret_cast<unsigned int*>(&lo);
    u.y = *reinterpret_cast<unsigned int*>(&hi);
    return u;
}
__device__ __forceinline__ float4 unpack_h4(uint2 u) {
    __half2 lo = *reinterpret_cast<__half2*>(&u.x);
    __half2 hi = *reinterpret_cast<__half2*>(&u.y);
    float2 a = __half22float2(lo);
    float2 b = __half22float2(hi);
    return make_float4(a.x, a.y, b.x, b.y);
}

// ---------------------------------------------------------------------------
// K1: fused SAME avg-pool 6x6 stride 4, oy-pair per CTA (R8 structure).
// smem column sums fp32; final average rounded once to fp16.
// ---------------------------------------------------------------------------
__global__ __launch_bounds__(288, 5) void pool_kernel(const float4* __restrict__ in4) {
    __shared__ float4 cs[2 * 288];    // [half][xl*16+c4]

    int bid = blockIdx.x;             // b*512 + p*16 + q
    int q = bid & 15;
    int p = (bid >> 4) & 31;
    int b = bid >> 9;

    int t  = threadIdx.x;             // 0..287
    int c4 = t & 15;
    int xl = t >> 4;                  // 0..17
    int x  = 16 * q - 1 + xl;
    int rbase = 8 * p - 1;

    float4 s0 = make_float4(0.f, 0.f, 0.f, 0.f);
    float4 s1 = make_float4(0.f, 0.f, 0.f, 0.f);

    if ((unsigned)x < 256u) {
        const float4* pr = in4 + (((size_t)b * HIN + rbase) * WIN + x) * CV4 + c4;
        const size_t RS = (size_t)WIN * CV4;
        if (p != 0 && p != 31) {
            float4 v0 = __ldg(pr + 0 * RS);
            float4 v1 = __ldg(pr + 1 * RS);
            float4 v2 = __ldg(pr + 2 * RS);
            float4 v3 = __ldg(pr + 3 * RS);
            acc4(s0, v0); acc4(s0, v1); acc4(s0, v2); acc4(s0, v3);
            float4 v4 = __ldg(pr + 4 * RS);
            float4 v5 = __ldg(pr + 5 * RS);
            acc4(s0, v4); acc4(s0, v5);
            acc4(s1, v4); acc4(s1, v5);
            float4 v6 = __ldg(pr + 6 * RS);
            float4 v7 = __ldg(pr + 7 * RS);
            float4 v8 = __ldg(pr + 8 * RS);
            float4 v9 = __ldg(pr + 9 * RS);
            acc4(s1, v6); acc4(s1, v7); acc4(s1, v8); acc4(s1, v9);
        } else {
            #pragma unroll
            for (int j = 0; j < 10; ++j) {
                int r = rbase + j;
                if ((unsigned)r < 256u) {
                    float4 v = __ldg(pr + (size_t)j * RS);
                    if (j <= 5) acc4(s0, v);
                    if (j >= 4) acc4(s1, v);
                }
            }
        }
    }
    cs[t]       = s0;
    cs[288 + t] = s1;
    __syncthreads();

    if (t < 128) {
        int cc4  = t & 15;
        int oxl  = (t >> 4) & 3;
        int half = t >> 6;            // 0 or 1
        int ox   = 4 * q + oxl;
        int oy   = 2 * p + half;

        const float4* base = cs + half * 288;
        float4 acc = make_float4(0.f, 0.f, 0.f, 0.f);
        if (ox != 0) acc4(acc, base[(4 * oxl + 0) * CV4 + cc4]);
        acc4(acc, base[(4 * oxl + 1) * CV4 + cc4]);
        acc4(acc, base[(4 * oxl + 2) * CV4 + cc4]);
        acc4(acc, base[(4 * oxl + 3) * CV4 + cc4]);
        acc4(acc, base[(4 * oxl + 4) * CV4 + cc4]);
        if (ox != 63) acc4(acc, base[(4 * oxl + 5) * CV4 + cc4]);

        int nr = 6 - (oy == 0) - (oy == 63);
        int nc = 6 - (ox == 0) - (ox == 63);
        float inv = 1.0f / (float)(nr * nc);
        float4 avg = make_float4(acc.x * inv, acc.y * inv, acc.z * inv, acc.w * inv);
        g_pooled[(((size_t)b * HP + oy) * WP + ox) * CV4 + cc4] = pack_h4(avg);
    }
}

// ---------------------------------------------------------------------------
// K2: unaverage pool, direct (R7-proven structure), fp16 tap loads (LDG.64).
// One thread = 8 consecutive x outputs (two k-groups) x one channel chunk.
// ---------------------------------------------------------------------------
__device__ __forceinline__ float d2s(float d) {
    if (d < 5.5f)   return (d - 2.0f) * (1.0f / 3.5f);
    if (d > 249.5f) return (d - 249.5f) * (1.0f / 3.5f) + 62.0f;
    return (d - 1.5f) * 0.25f;
}

__global__ __launch_bounds__(256, 6) void up_kernel(float4* __restrict__ out4) {
    int tid = blockIdx.x * 256 + threadIdx.x;   // B*256*32*16 = 1,048,576
    int c4 = tid & 15;
    int kk = (tid >> 4) & 31;
    int y  = (tid >> 9) & 255;
    int b  = tid >> 17;

    int k0 = kk * 2;

    float sr  = d2s((float)y);
    float r0f = floorf(sr);
    int   r0  = (int)r0f;
    float fr  = sr - r0f;
    bool rv0 = (r0 >= 0);
    bool rv1 = (r0 < HP - 1);
    float wr0 = 1.0f - fr;

    const uint2* pbase = g_pooled + ((size_t)b * HP * WP) * CV4 + c4;
    const uint2* rowA  = pbase + (size_t)(rv0 ? r0     : 0) * WP * CV4;
    const uint2* rowB  = pbase + (size_t)(rv1 ? r0 + 1 : 0) * WP * CV4;

    const float4 z = make_float4(0.f, 0.f, 0.f, 0.f);

    float4 T[4];
    #pragma unroll
    for (int i = 0; i < 4; ++i) {
        int col = k0 - 1 + i;
        bool cv = (unsigned)col < (unsigned)WP;
        float4 a  = (rv0 && cv) ? unpack_h4(__ldg(rowA + (size_t)col * CV4)) : z;
        float4 bb = (rv1 && cv) ? unpack_h4(__ldg(rowB + (size_t)col * CV4)) : z;
        T[i] = blend2(a, wr0, bb, fr);
    }

    float4* op = out4 + (((size_t)b * HIN + y) * WIN + k0 * 4) * CV4 + c4;

    if (kk >= 1 && kk <= 30) {
        op[0 * CV4] = blend2(T[0], 0.375f, T[1], 0.625f);
        op[1 * CV4] = blend2(T[0], 0.125f, T[1], 0.875f);
        op[2 * CV4] = blend2(T[1], 0.875f, T[2], 0.125f);
        op[3 * CV4] = blend2(T[1], 0.625f, T[2], 0.375f);
        op[4 * CV4] = blend2(T[1], 0.375f, T[2], 0.625f);
        op[5 * CV4] = blend2(T[1], 0.125f, T[2], 0.875f);
        op[6 * CV4] = blend2(T[2], 0.875f, T[3], 0.125f);
        op[7 * CV4] = blend2(T[2], 0.625f, T[3], 0.375f);
    } else {
        int x0 = k0 * 4;
        #pragma unroll
        for (int m = 0; m < 8; ++m) {
            float sc  = d2s((float)(x0 + m));
            float c0f = floorf(sc);
            float fc  = sc - c0f;
            int idx = (int)c0f - (k0 - 1);   // 0..2
            float4 lo = (idx == 0) ? T[0] : ((idx == 1) ? T[1] : T[2]);
            float4 hi = (idx == 0) ? T[1] : ((idx == 1) ? T[2] : T[3]);
            op[m * CV4] = blend2(lo, 1.0f - fc, hi, fc);
        }
    }
}

extern "C" void kernel_launch(void* const* d_in, const int* in_sizes, int n_in,
                              void* d_out, int out_size) {
    const float4* in4 = (const float4*)d_in[0];
    float4* out4 = (float4*)d_out;

    pool_kernel<<<B * 32 * 16, 288>>>(in4);               // 4096 CTAs
    up_kernel<<<(B * HIN * 32 * CV4) / 256, 256>>>(out4); // 4096 CTAs
}